// round 17
// baseline (speedup 1.0000x reference)
#include <cuda_runtime.h>
#include <cuda_bf16.h>

// Cascaded 16-tap FIR pair == single 33-tap causal conv for columns i >= 32:
//   y[i] = x[i] + sum_{j=1}^{32} g[j] * x[i-j],  g = [1,h] (*) [1,h_rev]
// Columns [0,32) computed exactly (v-mask aware) by lanes 0-1 on row-start tiles.
//
// ROW-PAIRED fma.rn.f32x2, RPT=16 cols/lane (512-col warp-tiles): window
// amplification 3x (vs 5x at RPT=8). THREADS=192, launch_bounds(192,2) ->
// 170-reg cap so the ~143-reg live set (wd[48] pairs + acc + taps) is truly
// register-resident (R16 failed at the 128 cap: regs=86 => spill/remat).
// Parity-plane interleaved tile (8-pair segments, 20-float padded stride,
// conflict-free at stride-2 segment access). cp4 staging-time interleave,
// triple-buffered depth-2 prefetch (R15), contiguous warp streams, no block
// barriers. Stores issued per-half to keep unpack temps transient.
//
// B=256 rows, N=131072 cols, F=16.

#define F       16
#define GT      33
#define THREADS 192
#define WARPS   6
#define WCOLS   512                // output columns per warp-tile (x 2 rows)
#define HALO    32
#define SPAN    (WCOLS + HALO)     // 544 staged columns
#define NCOL    131072
#define NROW    256
#define TPR     (NCOL / WCOLS)     // 256 tiles per row-pair
#define NWT     (TPR * (NROW / 2)) // 32768 warp-tiles
#define NBLK    296                // 2 CTAs per SM
#define NSTREAM (NBLK * WARPS)     // 1776 warp streams
#define QT      (NWT / NSTREAM)    // 18
#define RT      (NWT % NSTREAM)    // 800 streams get one extra

// Interleaved tile as two parity planes: 34 segments x 8 col-pairs each,
// padded 16 -> 20 floats per segment. Even plane @0, odd plane @EV.
#define EV      680                        // 34 * 20 floats
#define BUFW    (2 * EV)                   // 1360 floats per buffer
#define TAP_OFF (3 * BUFW)                 // 4080: 32 float2 tap pairs
#define WSLOT   (TAP_OFF + 64)             // 4144 floats per warp
#define SMEM_DYN (WARPS * WSLOT * 4)       // 99456 B

typedef unsigned long long u64;

#define FMA2(d, a, b, c) \
    asm("fma.rn.f32x2 %0, %1, %2, %3;" : "=l"(d) : "l"(a), "l"(b), "l"(c))
#define UNPACK2(lo, hi, p) \
    asm("mov.b64 {%0, %1}, %2;" : "=f"(lo), "=f"(hi) : "l"(p))

__device__ __forceinline__ void cp4(unsigned dst, const float* src, int sz) {
    asm volatile("cp.async.ca.shared.global [%0], [%1], 4, %2;"
                 :: "r"(dst), "l"(src), "r"(sz));
}
__device__ __forceinline__ void cp_commit() {
    asm volatile("cp.async.commit_group;");
}
template <int N> __device__ __forceinline__ void cp_wait() {
    asm volatile("cp.async.wait_group %0;" :: "n"(N));
}

// Stage warp-tile wt: staged col sc in [0,544) holds (x0[.], x1[.]) at
// plane((sc>>3)&1) + 20*(sc>>4) + 2*(sc&7) (+1 for row1).
__device__ __forceinline__ void stage_wt(unsigned sb, const float* x,
                                         int wt, int lane)
{
    const int p   = wt / TPR;
    const int tir = wt % TPR;
    const float* s0 = x + ((size_t)p * 2) * NCOL + tir * WCOLS - HALO;
    const float* s1 = s0 + NCOL;
    if (tir != 0) {
#pragma unroll
        for (int k = 0; k < SPAN / 32; k++) {      // 17 iters
            const int sc = lane + 32 * k;
            const unsigned d = sb +
                ((((sc >> 3) & 1) * EV + 20 * (sc >> 4) + 2 * (sc & 7)) << 2);
            cp4(d, s0 + sc, 4);
            cp4(d + 4, s1 + sc, 4);
        }
    } else {
#pragma unroll
        for (int k = 0; k < SPAN / 32; k++) {
            const int sc = lane + 32 * k;
            const int sz = (sc < HALO) ? 0 : 4;
            const float* a = sz ? (s0 + sc) : x;
            const float* b = sz ? (s1 + sc) : x;
            const unsigned d = sb +
                ((((sc >> 3) & 1) * EV + 20 * (sc >> 4) + 2 * (sc & 7)) << 2);
            cp4(d, a, sz);
            cp4(d + 4, b, sz);
        }
    }
}

// Load 8 pairs (one padded segment) into wd[0..8).
__device__ __forceinline__ void ld_seg(u64* wd, const float* p) {
#pragma unroll
    for (int q = 0; q < 4; q++) {
        const ulonglong2 v = *reinterpret_cast<const ulonglong2*>(p + 4 * q);
        wd[2 * q]     = v.x;
        wd[2 * q + 1] = v.y;
    }
}

__global__ __launch_bounds__(THREADS, 2)
void fir2_fused(const float* __restrict__ x,
                const float* __restrict__ h,
                float* __restrict__ y)
{
    extern __shared__ float smem[];

    const int tid  = threadIdx.x;
    const int wid  = tid >> 5;
    const int lane = tid & 31;

    float* const wbase = smem + wid * WSLOT;
    float* const tapf  = wbase + TAP_OFF;
    const unsigned sbw = (unsigned)__cvta_generic_to_shared(wbase);

    // ---- combined taps: lane computes g[lane+1], writes (g,g) to smem ------
    float hh[F];
#pragma unroll
    for (int j = 0; j < F; j++) hh[j] = __ldg(h + j);
    {
        const int j = lane + 1;                // 1..32
        float acc = 0.0f;
        const int a0 = (j > F) ? (j - F) : 0;
        const int a1 = (j < F) ? j : F;
#pragma unroll
        for (int a = 0; a <= F; a++) {
            if (a >= a0 && a <= a1) {
                const float ka = (a == 0) ? 1.0f : hh[a - 1];
                const int bb = j - a;
                const float kb = (bb == 0) ? 1.0f : hh[F - bb];
                acc += ka * kb;
            }
        }
        *reinterpret_cast<float2*>(tapf + 2 * lane) = make_float2(acc, acc);
    }
    __syncwarp();

    // ---- contiguous stream range -------------------------------------------
    const int S     = blockIdx.x * WARPS + wid;
    const int start = S * QT + ((S < RT) ? S : RT);
    const int cnt   = QT + (S < RT ? 1 : 0);

    // ---- prologue: stage tiles 0 and 1 of this stream ----------------------
    stage_wt(sbw, x, start, lane);
    cp_commit();
    stage_wt(sbw + BUFW * 4, x, start + 1, lane);
    cp_commit();

    for (int i = 0; i < cnt; i++) {
        cp_wait<1>();                      // tile i's group complete
        __syncwarp();                      // all lanes landed + done reading
                                           // buffer (i-1)%3
        if (i + 2 < cnt)
            stage_wt(sbw + ((i + 2) % 3) * (BUFW * 4), x, start + i + 2, lane);
        cp_commit();                       // always: group accounting stays aligned

        const int wt  = start + i;
        const int p   = wt / TPR;
        const int tir = wt % TPR;
        const int t0  = tir * WCOLS;
        const size_t r0off = (size_t)p * 2 * NCOL;
        const float* sxc = wbase + (i % 3) * BUFW;

        if (!(tir == 0 && lane < 2)) {
            // wd[q] = pair at staged col 16*lane + q, q in [0,48)
            u64 wd[48];
            ld_seg(wd,      sxc +      20 * lane);           // even k=0
            ld_seg(wd + 8,  sxc + EV + 20 * lane);           // odd  k=0
            ld_seg(wd + 16, sxc +      20 * (lane + 1));
            ld_seg(wd + 24, sxc + EV + 20 * (lane + 1));
            ld_seg(wd + 32, sxc +      20 * (lane + 2));
            ld_seg(wd + 40, sxc + EV + 20 * (lane + 2));

            float4* y0 = reinterpret_cast<float4*>(y + r0off + t0 + 16 * lane);
            float4* y1 = reinterpret_cast<float4*>(y + r0off + NCOL + t0 + 16 * lane);

#pragma unroll
            for (int half = 0; half < 2; half++) {
                const int ho = 8 * half;
                u64 acc[8];
#pragma unroll
                for (int r = 0; r < 8; r++) acc[r] = wd[32 + ho + r];
#pragma unroll
                for (int c = 0; c < 4; c++) {
                    u64 tq[8];
                    ld_seg(tq, tapf + 16 * c);               // broadcast LDS
#pragma unroll
                    for (int k = 1; k <= 8; k++) {
#pragma unroll
                        for (int r = 0; r < 8; r++)
                            FMA2(acc[r], tq[k - 1],
                                 wd[32 + ho + r - 8 * c - k], acc[r]);
                    }
                }
                // unpack + store this half immediately (temps stay transient)
                float o0[8], o1[8];
#pragma unroll
                for (int r = 0; r < 8; r++)
                    UNPACK2(o0[r], o1[r], acc[r]);
                y0[2 * half]     = make_float4(o0[0], o0[1], o0[2], o0[3]);
                y0[2 * half + 1] = make_float4(o0[4], o0[5], o0[6], o0[7]);
                y1[2 * half]     = make_float4(o1[0], o1[1], o1[2], o1[3]);
                y1[2 * half + 1] = make_float4(o1[4], o1[5], o1[6], o1[7]);
            }
        } else if (lane == 0) {
            // cols [0,16) = 0 for both rows
#pragma unroll
            for (int rr = 0; rr < 2; rr++) {
                float4* yo = reinterpret_cast<float4*>(y + r0off + rr * NCOL);
#pragma unroll
                for (int q = 0; q < 4; q++)
                    yo[q] = make_float4(0.f, 0.f, 0.f, 0.f);
            }
        } else {
            // lane 1: exact masked two-stage result, cols [16,32), both rows
#pragma unroll
            for (int rr = 0; rr < 2; rr++) {
                const float* xr = x + r0off + rr * NCOL;
                float xa[32];
#pragma unroll
                for (int cc = 0; cc < 32; cc++) xa[cc] = xr[cc];

                float va[F];               // v[16..31]
#pragma unroll
                for (int tt = 0; tt < F; tt++) {
                    const int k = F + tt;
                    float a2 = xa[k];
#pragma unroll
                    for (int j = 0; j < F; j++)
                        a2 = fmaf(hh[j], xa[k - 1 - j], a2);
                    va[tt] = a2;
                }
                float ya[F];               // y[16..31]
#pragma unroll
                for (int tt = 0; tt < F; tt++) {
                    const int i2 = F + tt;
                    float a2 = va[tt];
#pragma unroll
                    for (int m = 0; m < F; m++) {
                        const int k = i2 - F + m;  // v index; masked if < 16
                        if (k >= F) a2 = fmaf(hh[m], va[k - F], a2);
                    }
                    ya[tt] = a2;
                }
                float4* yo = reinterpret_cast<float4*>(y + r0off + rr * NCOL + F);
#pragma unroll
                for (int q = 0; q < 4; q++)
                    yo[q] = make_float4(ya[4 * q], ya[4 * q + 1],
                                        ya[4 * q + 2], ya[4 * q + 3]);
            }
        }
    }
}

extern "C" void kernel_launch(void* const* d_in, const int* in_sizes, int n_in,
                              void* d_out, int out_size)
{
    const float* x = (const float*)d_in[0];   // (256, 131072) f32
    const float* h = (const float*)d_in[1];   // (1, 16) f32
    float* y = (float*)d_out;                 // (256, 131072) f32

    cudaFuncSetAttribute(fir2_fused,
                         cudaFuncAttributeMaxDynamicSharedMemorySize, SMEM_DYN);
    fir2_fused<<<NBLK, THREADS, SMEM_DYN>>>(x, h, y);
}